// round 15
// baseline (speedup 1.0000x reference)
#include <cuda_runtime.h>
#include <cstdint>

typedef unsigned long long ull;

// ---------------------------------------------------------------- helpers
__device__ __forceinline__ ull pack2(float lo, float hi) {
    ull r; asm("mov.b64 %0, {%1, %2};" : "=l"(r) : "f"(lo), "f"(hi)); return r;
}
__device__ __forceinline__ void unpack2(ull v, float& lo, float& hi) {
    asm("mov.b64 {%0, %1}, %2;" : "=f"(lo), "=f"(hi) : "l"(v));
}
__device__ __forceinline__ ull fma2(ull a, ull b, ull c) {
    ull d; asm("fma.rn.f32x2 %0, %1, %2, %3;" : "=l"(d) : "l"(a), "l"(b), "l"(c)); return d;
}
__device__ __forceinline__ float ex2f(float x) {
    float y; asm("ex2.approx.f32 %0, %1;" : "=f"(y) : "f"(x)); return y;
}
__device__ __forceinline__ float to_tf32(float x) {
    uint32_t o; asm("cvt.rna.tf32.f32 %0, %1;" : "=r"(o) : "f"(x));
    return __uint_as_float(o);
}
__device__ __forceinline__ uint32_t smem_u32(const void* p) {
    uint32_t a;
    asm("{ .reg .u64 t; cvta.to.shared.u64 t, %1; cvt.u32.u64 %0, t; }" : "=r"(a) : "l"(p));
    return a;
}
__device__ __forceinline__ void mma8(float* c, const uint32_t* a, const uint32_t* b) {
    asm volatile(
        "mma.sync.aligned.m16n8k8.row.col.f32.tf32.tf32.f32 "
        "{%0,%1,%2,%3}, {%4,%5,%6,%7}, {%8,%9}, {%0,%1,%2,%3};"
        : "+f"(c[0]), "+f"(c[1]), "+f"(c[2]), "+f"(c[3])
        : "r"(a[0]), "r"(a[1]), "r"(a[2]), "r"(a[3]), "r"(b[0]), "r"(b[1]));
}
__device__ __forceinline__ void mbar_init(uint32_t m, uint32_t cnt) {
    asm volatile("mbarrier.init.shared.b64 [%0], %1;" :: "r"(m), "r"(cnt) : "memory");
}
__device__ __forceinline__ void mbar_expect(uint32_t m, uint32_t bytes) {
    asm volatile("mbarrier.arrive.expect_tx.shared.b64 _, [%0], %1;"
                 :: "r"(m), "r"(bytes) : "memory");
}
__device__ __forceinline__ void mbar_wait(uint32_t m, uint32_t ph) {
    asm volatile(
        "{\n\t"
        ".reg .pred P1;\n\t"
        "LAB_%=:\n\t"
        "mbarrier.try_wait.parity.acquire.cta.shared::cta.b64 P1, [%0], %1, 0x989680;\n\t"
        "@P1 bra.uni DONE_%=;\n\t"
        "bra.uni LAB_%=;\n\t"
        "DONE_%=:\n\t"
        "}"
        :: "r"(m), "r"(ph) : "memory");
}
__device__ __forceinline__ void bulk_cp(uint32_t dst, const void* src,
                                        uint32_t bytes, uint32_t mbar) {
    asm volatile(
        "cp.async.bulk.shared::cluster.global.mbarrier::complete_tx::bytes "
        "[%0], [%1], %2, [%3];"
        :: "r"(dst), "l"(src), "r"(bytes), "r"(mbar) : "memory");
}

#define BB    8
#define CC    20
#define TT    15000
#define HW    625
#define CHS   872          // halo channel: 27 rows x 32 + 8 pad; halos stay zero

// interior pixel p -> halo layout offset
#define YXH(p) (((p) / 25) * 32 + ((p) % 25) + 33)

// memread MMA config
#define NTS2  18           // 288 blocks = one wave at 2 blocks/SM
#define TSEG2 864          // 18*864 = 15552 >= 15000 (tail rows zero)
#define TC2   32
#define TROWS 15552
#define QT2   2
#define QROWS 640

// scratch (device globals: allocation-free, zero-initialized at load;
// halo/pad regions are never written so they remain zero)
__device__ __align__(16) float g_y[BB * 40 * CHS];
__device__ __align__(16) float g_buf[2][2][BB * 256 * CHS];
__device__ __align__(16) float g_pa[BB * NTS2 * QROWS * 24];
// transposed fm: [b][t 15552][c 28] (c=20 ones, 21..27 zero, t>=15000 zero)
__device__ __align__(16) float g_fmT[BB * TROWS * 28];

// prepped weights, padded to smem-native stride 136: per chunk [72][136]
#define CHUNK_W 9792
#define ST_STRIDE 3858048     // 2*5*9792 + 6*2*32*9792
#define WPREP_TOTAL (2 * ST_STRIDE)
__device__ __align__(16) float g_wprep[WPREP_TOTAL];

__global__ void noop_kernel() {}

// ---------------------------------------------------------------------------
// fm transpose: [b][c][t] -> [b][t][28] with ones channel (c=20) baked in.
// grid (59, 8), block 256.
// ---------------------------------------------------------------------------
__global__ void __launch_bounds__(256)
transpose_fm(const float* __restrict__ fm) {
    __shared__ float tl[20][257];
    const int b = blockIdx.y;
    const int t0 = blockIdx.x * 256;
    const int tid = threadIdx.x;
    for (int i = tid; i < 20 * 256; i += 256) {
        int c = i >> 8, tt = i & 255;
        int tg = t0 + tt;
        tl[c][tt] = (tg < TT) ? fm[(size_t)(b * CC + c) * TT + tg] : 0.f;
    }
    __syncthreads();
    for (int i = tid; i < 256 * 21; i += 256) {
        int tt = i / 21, c = i - tt * 21;
        int tg = t0 + tt;
        if (tg < TT)
            g_fmT[((size_t)b * TROWS + tg) * 28 + c] = (c < CC) ? tl[c][tt] : 1.f;
    }
}

// ---------------------------------------------------------------------------
// weight prep (transpose via smem) -> [kt 72][136] per chunk
// ---------------------------------------------------------------------------
__global__ void __launch_bounds__(256)
prep_weights2(const float* __restrict__ cls1_w,
              const float* __restrict__ clsk_w,
              const float* __restrict__ reg1_w,
              const float* __restrict__ regk_w) {
    __shared__ float smt[72 * 128];
    const int chunk = blockIdx.x;
    const int l = blockIdx.y;
    const int sb = blockIdx.z;
    const int s = sb >> 1, ocb = sb & 1;
    const int nch = (l == 0) ? 5 : 32;
    if (chunk >= nch) return;
    const int tid = threadIdx.x;

    const float* src;
    int srcK;
    if (l == 0) {
        src = s ? reg1_w : cls1_w; srcK = 360;
    } else {
        src = (s ? regk_w : clsk_w) + (size_t)(l - 1) * 256 * 2304; srcK = 2304;
    }

    {
        const int r = tid >> 1, part = tid & 1;
        const float4* srow = (const float4*)(src +
            (size_t)(ocb * 128 + r) * srcK + chunk * 72);
#pragma unroll
        for (int j4 = 0; j4 < 9; j4++) {
            float4 v = srow[part * 9 + j4];
            int j = (part * 9 + j4) * 4;
            smt[(j + 0) * 128 + r] = v.x;
            smt[(j + 1) * 128 + r] = v.y;
            smt[(j + 2) * 128 + r] = v.z;
            smt[(j + 3) * 128 + r] = v.w;
        }
    }
    __syncthreads();

    float* dst = g_wprep + (size_t)s * ST_STRIDE +
                 (l == 0 ? 0 : 97920 + (size_t)(l - 1) * 626688) +
                 (size_t)ocb * nch * CHUNK_W + (size_t)chunk * CHUNK_W;
#pragma unroll
    for (int it = 0; it < 36; it++) {
        int w_i = it * 256 + tid;
        int m = w_i & 127;
        int kt = w_i >> 7;              // tap*8 + k
        int tap = kt >> 3, k = kt & 7;
        dst[kt * 136 + m] = to_tf32(smt[(k * 9 + tap) * 128 + m]);
    }
}

// ---------------------------------------------------------------------------
// memory_read: pure tf32, log2-domain, dual-pipe exp; staging now via
// double-buffered cp.async.bulk from pre-transposed g_fmT (3.6KB/chunk).
// grid (2, 18, 8) = 288 blocks, 2 blocks/SM -> one wave.
// ---------------------------------------------------------------------------
#define FMST 28
#define PST  36
#define MR_FM0 4
#define MR_FM1 (4 + TC2 * FMST)
#define MR_P0  (4 + 2 * TC2 * FMST)
#define MR_SMEM_FLOATS (4 + 2 * TC2 * FMST + 10 * TC2 * PST)
#define MR_SMEM_BYTES (MR_SMEM_FLOATS * 4)
#define FM_BYTES (TC2 * FMST * 4)

__global__ void __launch_bounds__(320, 2)
memread_mma(const float* __restrict__ fq) {
    extern __shared__ float ms[];
    const uint32_t sbase = smem_u32(ms);
    const uint32_t mbar0 = sbase;
    const uint32_t mbar1 = sbase + 8;
    const int tid = threadIdx.x;
    const int lane = tid & 31, w = tid >> 5;
    const int qt = blockIdx.x, ts = blockIdx.y, b = blockIdx.z;
    const int qbase = qt * 320 + w * 32;
    float* P = ms + MR_P0 + w * (TC2 * PST);

    const int mrow = lane >> 2;
    const int kcol = lane & 3;
    const float scale = 0.063758726f;          // log2(e)/sqrt(512)

    const ull C7 = pack2(1.5252734e-05f, 1.5252734e-05f);
    const ull C6 = pack2(1.5403530e-04f, 1.5403530e-04f);
    const ull C5 = pack2(1.3333558e-03f, 1.3333558e-03f);
    const ull C4 = pack2(9.6181291e-03f, 9.6181291e-03f);
    const ull C3 = pack2(5.5504109e-02f, 5.5504109e-02f);
    const ull C2 = pack2(2.4022651e-01f, 2.4022651e-01f);
    const ull C1 = pack2(6.9314718e-01f, 6.9314718e-01f);
    const ull ONE2 = pack2(1.0f, 1.0f);

    if (tid == 0) {
        mbar_init(mbar0, 1);
        mbar_init(mbar1, 1);
        asm volatile("fence.proxy.async.shared::cta;" ::: "memory");
    }
    __syncthreads();

    uint32_t a_f[2][3][4];
#pragma unroll
    for (int mf = 0; mf < 2; mf++)
#pragma unroll
        for (int kf = 0; kf < 3; kf++)
#pragma unroll
            for (int j = 0; j < 4; j++) {
                int q = qbase + 16 * mf + mrow + 8 * (j & 1);
                int c = kf * 8 + kcol + 4 * (j >> 1);
                float v = (q < HW && c < CC) ? fq[(b * CC + c) * HW + q] * scale : 0.f;
                a_f[mf][kf][j] = __float_as_uint(to_tf32(v));
            }

    float acc[2][3][4];
#pragma unroll
    for (int mf = 0; mf < 2; mf++)
#pragma unroll
        for (int nf = 0; nf < 3; nf++)
#pragma unroll
            for (int j = 0; j < 4; j++) acc[mf][nf][j] = 0.f;

    const float* seg = g_fmT + ((size_t)b * TROWS + ts * TSEG2) * 28;
    const int NCH = TSEG2 / TC2;   // 27

    if (tid == 0) {
        mbar_expect(mbar0, FM_BYTES);
        bulk_cp(sbase + MR_FM0 * 4, seg, FM_BYTES, mbar0);
    }

    for (int ch = 0; ch < NCH; ch++) {
        const int p = ch & 1;
        if (ch + 1 < NCH && tid == 0) {
            uint32_t mb = p ? mbar0 : mbar1;
            mbar_expect(mb, FM_BYTES);
            bulk_cp(sbase + (p ? MR_FM0 : MR_FM1) * 4,
                    seg + (size_t)(ch + 1) * TC2 * 28, FM_BYTES, mb);
        }
        mbar_wait(p ? mbar1 : mbar0, (ch >> 1) & 1);
        const float* fm_s = ms + (p ? MR_FM1 : MR_FM0);

        // ---- GEMM1: z^T (32q x 32t)
        float s[2][4][4];
#pragma unroll
        for (int mf = 0; mf < 2; mf++)
#pragma unroll
            for (int nf = 0; nf < 4; nf++)
#pragma unroll
                for (int j = 0; j < 4; j++) s[mf][nf][j] = 0.f;

#pragma unroll
        for (int kf = 0; kf < 3; kf++) {
            uint32_t bh[4][2];
#pragma unroll
            for (int nf = 0; nf < 4; nf++) {
                int ta = (nf * 8 + mrow) * FMST + kf * 8 + kcol;
                bh[nf][0] = __float_as_uint(fm_s[ta]);
                bh[nf][1] = __float_as_uint(fm_s[ta + 4]);
            }
#pragma unroll
            for (int mf = 0; mf < 2; mf++)
#pragma unroll
                for (int nf = 0; nf < 4; nf++)
                    mma8(s[mf][nf], a_f[mf][kf], bh[nf]);
        }

        // ---- p = 2^z: dual-pipe exp
#pragma unroll
        for (int mf = 0; mf < 2; mf++) {
#pragma unroll
            for (int nf = 0; nf < 4; nf++) {
                float p0, p1, p2, p3;
                if (nf < 2) {
                    ull za = pack2(s[mf][nf][0], s[mf][nf][1]);
                    ull zb = pack2(s[mf][nf][2], s[mf][nf][3]);
                    ull ra = fma2(C7, za, C6);
                    ull rb = fma2(C7, zb, C6);
                    ra = fma2(ra, za, C5); rb = fma2(rb, zb, C5);
                    ra = fma2(ra, za, C4); rb = fma2(rb, zb, C4);
                    ra = fma2(ra, za, C3); rb = fma2(rb, zb, C3);
                    ra = fma2(ra, za, C2); rb = fma2(rb, zb, C2);
                    ra = fma2(ra, za, C1); rb = fma2(rb, zb, C1);
                    ra = fma2(ra, za, ONE2); rb = fma2(rb, zb, ONE2);
                    unpack2(ra, p0, p1);
                    unpack2(rb, p2, p3);
                } else {
                    p0 = ex2f(s[mf][nf][0]);
                    p1 = ex2f(s[mf][nf][1]);
                    p2 = ex2f(s[mf][nf][2]);
                    p3 = ex2f(s[mf][nf][3]);
                }
                int row = 16 * mf + mrow;
                int col = nf * 8 + 2 * kcol;
                P[row * PST + col] = p0;
                P[row * PST + col + 1] = p1;
                P[(row + 8) * PST + col] = p2;
                P[(row + 8) * PST + col + 1] = p3;
            }
        }
        __syncwarp();

        // ---- GEMM2: mem^T (32q x 24c2)
#pragma unroll
        for (int kf2 = 0; kf2 < 4; kf2++) {
            uint32_t ph[2][4];
#pragma unroll
            for (int mf = 0; mf < 2; mf++)
#pragma unroll
                for (int j = 0; j < 4; j++) {
                    int row = 16 * mf + mrow + 8 * (j & 1);
                    int col = kf2 * 8 + kcol + 4 * (j >> 1);
                    ph[mf][j] = __float_as_uint(P[row * PST + col]);
                }
            uint32_t bh2[3][2];
#pragma unroll
            for (int nf = 0; nf < 3; nf++) {
                int i0 = (kf2 * 8 + kcol) * FMST + nf * 8 + mrow;
                int i1 = (kf2 * 8 + kcol + 4) * FMST + nf * 8 + mrow;
                bh2[nf][0] = __float_as_uint(fm_s[i0]);
                bh2[nf][1] = __float_as_uint(fm_s[i1]);
            }
#pragma unroll
            for (int mf = 0; mf < 2; mf++)
#pragma unroll
                for (int nf = 0; nf < 3; nf++)
                    mma8(acc[mf][nf], ph[mf], bh2[nf]);
        }
        __syncthreads();   // all reads of slot p done before it is restaged
    }

    const size_t base = (size_t)(b * NTS2 + ts) * QROWS;
#pragma unroll
    for (int mf = 0; mf < 2; mf++) {
        int row0 = qbase + 16 * mf + mrow;
#pragma unroll
        for (int nf = 0; nf < 3; nf++) {
            int col = nf * 8 + 2 * kcol;
            float2 v0 = make_float2(acc[mf][nf][0], acc[mf][nf][1]);
            float2 v1 = make_float2(acc[mf][nf][2], acc[mf][nf][3]);
            *(float2*)(g_pa + (base + row0) * 24 + col) = v0;
            *(float2*)(g_pa + (base + row0 + 8) * 24 + col) = v1;
        }
    }
}

// ---------------------------------------------------------------------------
// combine: writes interior of halo layout g_y
// ---------------------------------------------------------------------------
__global__ void memread_combine2(const float* __restrict__ fq) {
    const int b = blockIdx.y;
    if (threadIdx.x >= 125) return;
    const int q = blockIdx.x * 125 + threadIdx.x;
    const int yx = YXH(q);
    float num[20];
#pragma unroll
    for (int c = 0; c < CC; c++) num[c] = 0.f;
    float den = 0.f;
    for (int ts = 0; ts < NTS2; ts++) {
        const float4* p = (const float4*)(g_pa +
            ((size_t)(b * NTS2 + ts) * QROWS + q) * 24);
        float4 v0 = p[0], v1 = p[1], v2 = p[2], v3 = p[3], v4 = p[4], v5 = p[5];
        num[0] += v0.x; num[1] += v0.y; num[2] += v0.z; num[3] += v0.w;
        num[4] += v1.x; num[5] += v1.y; num[6] += v1.z; num[7] += v1.w;
        num[8] += v2.x; num[9] += v2.y; num[10] += v2.z; num[11] += v2.w;
        num[12] += v3.x; num[13] += v3.y; num[14] += v3.z; num[15] += v3.w;
        num[16] += v4.x; num[17] += v4.y; num[18] += v4.z; num[19] += v4.w;
        den += v5.x;
    }
    const float inv = 1.f / den;
#pragma unroll
    for (int c = 0; c < CC; c++)
        g_y[(b * 40 + c) * CHS + yx] = to_tf32(num[c] * inv);
#pragma unroll
    for (int c = 0; c < CC; c++)
        g_y[(b * 40 + 20 + c) * CHS + yx] = to_tf32(fq[(b * CC + c) * HW + q]);
}

// ---------------------------------------------------------------------------
// TF32 conv (R14 winner, unchanged): bulk staging + pipelined taps, 8 warps
// ---------------------------------------------------------------------------
#define TBF 6976           // B tile floats (8 * 872)
#define TAF 9792           // A tile floats (72 * 136)
#define OFF_B0 8
#define OFF_B1 (8 + TBF)
#define OFF_A0 (8 + 2 * TBF)
#define OFF_A1 (8 + 2 * TBF + TAF)
#define SMEM_FLOATS (8 + 2 * TBF + 2 * TAF)
#define SMEM_BYTES (SMEM_FLOATS * 4)
#define B_BYTES (TBF * 4)
#define A_BYTES (TAF * 4)

__device__ __forceinline__ void load_frags(
    const uint32_t* __restrict__ bAu32, const uint32_t* __restrict__ bBu32,
    int tap, int wm, int a_r, int a_c, const int* bslot, int kofs,
    uint32_t afr[4][4], uint32_t bfr[5][2]) {
    const int dy = tap / 3, dx = tap - 3 * (tap / 3);
    const int arow = (tap * 8 + a_c) * 136;
#pragma unroll
    for (int mf = 0; mf < 4; mf++) {
        int m0 = wm + mf * 16 + a_r;
        afr[mf][0] = bAu32[arow + m0];
        afr[mf][1] = bAu32[arow + m0 + 8];
        afr[mf][2] = bAu32[arow + 4 * 136 + m0];
        afr[mf][3] = bAu32[arow + 4 * 136 + m0 + 8];
    }
#pragma unroll
    for (int nf = 0; nf < 5; nf++) {
        int idx = kofs + bslot[nf] + dy * 32 + dx;
        bfr[nf][0] = bBu32[idx];
        bfr[nf][1] = bBu32[idx + 4 * 872];
    }
}

__global__ void __launch_bounds__(256, 1)
convgemm(const float* __restrict__ biasA, const float* __restrict__ biasB,
         int layer, int nch, int flags, int src, int dst) {
    extern __shared__ float sm[];
    const uint32_t sbase = smem_u32(sm);
    const uint32_t mbar0 = sbase;
    const uint32_t mbar1 = sbase + 8;

    const int tid = threadIdx.x;
    const int lane = tid & 31, wid = tid >> 5;    // 8 warps
    const int ocb = blockIdx.x & 1;
    const int px = blockIdx.x >> 1;               // 0..3
    const int b = blockIdx.y;
    const int st = blockIdx.z;

    const int wm = (wid & 1) * 64;                // 2 m-warps
    const int wn = (wid >> 1) * 40;               // 4 n-warps
    const int BN0 = px * 160;

    const float* in_ = (src < 0) ? (g_y + (size_t)b * 40 * CHS)
                                 : (&g_buf[st][src][(size_t)b * 256 * CHS]);
    float* out_ = &g_buf[st][dst][((size_t)b * 256 + ocb * 128) * CHS];
    const float* bias_ = (st ? biasB : biasA) + ocb * 128;
    const float* wl = g_wprep + (size_t)st * ST_STRIDE +
                      (layer == 0 ? 0 : 97920 + (size_t)(layer - 1) * 626688) +
                      (size_t)ocb * nch * CHUNK_W;

    if (tid == 0) {
        mbar_init(mbar0, 1);
        mbar_init(mbar1, 1);
        asm volatile("fence.proxy.async.shared::cta;" ::: "memory");
    }
    __syncthreads();

    const int a_r = lane >> 2;
    const int a_c = lane & 3;
    int bslot[5];
#pragma unroll
    for (int nf = 0; nf < 5; nf++) {
        int p = BN0 + wn + nf * 8 + a_r;
        int y = p / 25, x = p - 25 * y;
        bslot[nf] = y * 32 + x;
    }
    const int kofs = a_c * 872;

    float cr[4][5][4];
#pragma unroll
    for (int mf = 0; mf < 4; mf++)
#pragma unroll
        for (int nf = 0; nf < 5; nf++)
#pragma unroll
            for (int j = 0; j < 4; j++) cr[mf][nf][j] = 0.f;

    if (tid == 0) {
        mbar_expect(mbar0, B_BYTES + A_BYTES);
        bulk_cp(sbase + OFF_B0 * 4, in_, B_BYTES, mbar0);
        bulk_cp(sbase + OFF_A0 * 4, wl, A_BYTES, mbar0);
    }

    for (int c = 0; c < nch; c++) {
        const int p = c & 1;
        if (c + 1 < nch) {
            if (tid == 0) {
                uint32_t mb = p ? mbar0 : mbar1;
                mbar_expect(mb, B_BYTES + A_BYTES);
                bulk_cp(sbase + (p ? OFF_B0 : OFF_B1) * 4,
                        in_ + (size_t)(c + 1) * 8 * CHS, B_BYTES, mb);
                bulk_cp(sbase + (p ? OFF_A0 : OFF_A1) * 4,
                        wl + (size_t)(c + 1) * CHUNK_W, A_BYTES, mb);
            }
        }
        mbar_wait(p ? mbar1 : mbar0, (c >> 1) & 1);

        const uint32_t* bBu32 = (const uint32_t*)(sm + (p ? OFF_B1 : OFF_B0));
        const uint32_t* bAu32 = (const uint32_t*)(sm + (p ? OFF_A1 : OFF_A0));

        uint32_t afr[2][4][4], bfr[2][5][2];
        load_frags(bAu32, bBu32, 0, wm, a_r, a_c, bslot, kofs, afr[0], bfr[0]);
#pragma unroll
        for (int tap = 0; tap < 9; tap++) {
            const int cur = tap & 1;
            if (tap < 8)
                load_frags(bAu32, bBu32, tap + 1, wm, a_r, a_c, bslot, kofs,
                           afr[cur ^ 1], bfr[cur ^ 1]);
#pragma unroll
            for (int mf = 0; mf < 4; mf++)
#pragma unroll
                for (int nf = 0; nf < 5; nf++)
                    mma8(cr[mf][nf], afr[cur][mf], bfr[cur][nf]);
        }
        __syncthreads();
    }

    const int ccol = (lane & 3) * 2;
    const bool relu = flags & 1, rnd = flags & 2;
#pragma unroll
    for (int mf = 0; mf < 4; mf++) {
        int r0 = wm + mf * 16 + a_r;
        float bv0 = bias_[r0], bv1 = bias_[r0 + 8];
        float* o0 = out_ + (size_t)r0 * CHS;
        float* o1 = o0 + (size_t)8 * CHS;
#pragma unroll
        for (int nf = 0; nf < 5; nf++) {
            int p = BN0 + wn + nf * 8 + ccol;
            float v0 = cr[mf][nf][0] + bv0;
            float v1 = cr[mf][nf][1] + bv0;
            float v2 = cr[mf][nf][2] + bv1;
            float v3 = cr[mf][nf][3] + bv1;
            if (relu) {
                v0 = fmaxf(v0, 0.f); v1 = fmaxf(v1, 0.f);
                v2 = fmaxf(v2, 0.f); v3 = fmaxf(v3, 0.f);
            }
            if (rnd) {
                v0 = to_tf32(v0); v1 = to_tf32(v1);
                v2 = to_tf32(v2); v3 = to_tf32(v3);
            }
            if (p < HW) {
                int yx = YXH(p);
                o0[yx] = v0; o1[yx] = v2;
            }
            if (p + 1 < HW) {
                int yx1 = YXH(p + 1);
                o0[yx1] = v1; o1[yx1] = v3;
            }
        }
    }
}

// ---------------------------------------------------------------------------
// heads (halo-layout reads)
// ---------------------------------------------------------------------------
__global__ void head_kernel(
    const float* __restrict__ w_cls, const float* __restrict__ b_cls,
    const float* __restrict__ g_cls, const float* __restrict__ be_cls,
    const float* __restrict__ w_ctr, const float* __restrict__ b_ctr,
    const float* __restrict__ g_ctr, const float* __restrict__ be_ctr,
    const float* __restrict__ w_off, const float* __restrict__ b_off,
    const float* __restrict__ g_off, const float* __restrict__ be_off,
    const float* __restrict__ si, const float* __restrict__ bi,
    float* __restrict__ out) {
    const int b = blockIdx.y;
    const int tid = threadIdx.x;
    __shared__ float sw[6 * 256];
    for (int i = tid; i < 256; i += 128) {
        sw[i] = w_cls[i];
        sw[256 + i] = w_ctr[i];
#pragma unroll
        for (int j = 0; j < 4; j++) sw[(2 + j) * 256 + i] = w_off[j * 256 + i];
    }
    __syncthreads();
    if (tid >= 125) return;

    const int p = blockIdx.x * 125 + tid;
    const int yx = YXH(p);
    const float rsq = rsqrtf(1.f + 1e-5f);
    const float scls = g_cls[0] * rsq, sctr = g_ctr[0] * rsq;
    const float sV = si[0], bV = bi[0];

    float d0 = 0, d1 = 0, d2 = 0, d3 = 0, d4 = 0, d5 = 0;
    const float* fc = g_buf[0][0] + (size_t)(b * 256) * CHS + yx;
    const float* fr = g_buf[1][0] + (size_t)(b * 256) * CHS + yx;
#pragma unroll 4
    for (int c = 0; c < 256; c++) {
        float vc = fc[(size_t)c * CHS];
        float vr = fr[(size_t)c * CHS];
        d0 += vc * sw[c];
        d1 += vc * sw[256 + c];
        d2 += vr * sw[512 + c];
        d3 += vr * sw[768 + c];
        d4 += vr * sw[1024 + c];
        d5 += vr * sw[1280 + c];
    }
    float cls = (d0 + b_cls[0]) * scls + be_cls[0];
    float ctr = (d1 + b_ctr[0]) * sctr + be_ctr[0];
    float dd[4] = {d2, d3, d4, d5};
    float off[4];
#pragma unroll
    for (int j = 0; j < 4; j++) {
        float bn = (dd[j] + b_off[j]) * (g_off[j] * rsq) + be_off[j];
        off[j] = expf(sV * bn + bV) * 8.f;
    }
    float gx = 3.f + 8.f * (float)(p % 25);
    float gy = 3.f + 8.f * (float)(p / 25);
    int qi = b * HW + p;
    out[qi] = cls;
    out[5000 + qi] = ctr;
    float* bb = out + 10000 + (size_t)qi * 4;
    bb[0] = gx - off[0];
    bb[1] = gy - off[1];
    bb[2] = gx + off[2];
    bb[3] = gy + off[3];
}

// ---------------------------------------------------------------------------
extern "C" void kernel_launch(void* const* d_in, const int* in_sizes, int n_in,
                              void* d_out, int out_size) {
    const float* fm     = (const float*)d_in[0];
    const float* fq     = (const float*)d_in[1];
    const float* cls1_w = (const float*)d_in[2];
    const float* cls1_b = (const float*)d_in[3];
    const float* clsk_w = (const float*)d_in[4];
    const float* clsk_b = (const float*)d_in[5];
    const float* reg1_w = (const float*)d_in[6];
    const float* reg1_b = (const float*)d_in[7];
    const float* regk_w = (const float*)d_in[8];
    const float* regk_b = (const float*)d_in[9];
    const float* w_cls  = (const float*)d_in[10];
    const float* b_cls  = (const float*)d_in[11];
    const float* g_cls  = (const float*)d_in[12];
    const float* be_cls = (const float*)d_in[13];
    const float* w_ctr  = (const float*)d_in[14];
    const float* b_ctr  = (const float*)d_in[15];
    const float* g_ctr  = (const float*)d_in[16];
    const float* be_ctr = (const float*)d_in[17];
    const float* w_off  = (const float*)d_in[18];
    const float* b_off  = (const float*)d_in[19];
    const float* g_off  = (const float*)d_in[20];
    const float* be_off = (const float*)d_in[21];
    const float* si     = (const float*)d_in[22];
    const float* bi     = (const float*)d_in[23];
    float* out = (float*)d_out;

    cudaFuncSetAttribute(convgemm, cudaFuncAttributeMaxDynamicSharedMemorySize,
                         SMEM_BYTES);
    cudaFuncSetAttribute(memread_mma, cudaFuncAttributeMaxDynamicSharedMemorySize,
                         MR_SMEM_BYTES);

    // launch order: prep(1) transpose(2) noop(3) memread(4 = ncu capture slot)
    prep_weights2<<<dim3(32, 7, 4), 256>>>(cls1_w, clsk_w, reg1_w, regk_w);
    transpose_fm<<<dim3(59, BB), 256>>>(fm);
    noop_kernel<<<1, 32>>>();

    memread_mma<<<dim3(QT2, NTS2, BB), 320, MR_SMEM_BYTES>>>(fq);
    memread_combine2<<<dim3(5, BB), 128>>>(fq);

    // conv1: Cin=40 (5 chunks), output relu+round, g_y -> buf 0
    convgemm<<<dim3(8, BB, 2), 256, SMEM_BYTES>>>(cls1_b, reg1_b, 0, 5, 3, -1, 0);

    // 6 x conv 256->256, ping-pong; final layer raw
    for (int i = 0; i < 6; i++) {
        convgemm<<<dim3(8, BB, 2), 256, SMEM_BYTES>>>(
            clsk_b + i * 256, regk_b + i * 256,
            i + 1, 32, (i < 5) ? 3 : 0, i % 2, (i + 1) % 2);
    }

    head_kernel<<<dim3(5, BB), 128>>>(w_cls, b_cls, g_cls, be_cls,
                                      w_ctr, b_ctr, g_ctr, be_ctr,
                                      w_off, b_off, g_off, be_off,
                                      si, bi, out);
}

// round 17
// speedup vs baseline: 1.5145x; 1.5145x over previous
#include <cuda_runtime.h>
#include <cstdint>

typedef unsigned long long ull;

// ---------------------------------------------------------------- helpers
__device__ __forceinline__ ull pack2(float lo, float hi) {
    ull r; asm("mov.b64 %0, {%1, %2};" : "=l"(r) : "f"(lo), "f"(hi)); return r;
}
__device__ __forceinline__ void unpack2(ull v, float& lo, float& hi) {
    asm("mov.b64 {%0, %1}, %2;" : "=f"(lo), "=f"(hi) : "l"(v));
}
__device__ __forceinline__ ull fma2(ull a, ull b, ull c) {
    ull d; asm("fma.rn.f32x2 %0, %1, %2, %3;" : "=l"(d) : "l"(a), "l"(b), "l"(c)); return d;
}
__device__ __forceinline__ float ex2f(float x) {
    float y; asm("ex2.approx.f32 %0, %1;" : "=f"(y) : "f"(x)); return y;
}
__device__ __forceinline__ float to_tf32(float x) {
    uint32_t o; asm("cvt.rna.tf32.f32 %0, %1;" : "=r"(o) : "f"(x));
    return __uint_as_float(o);
}
__device__ __forceinline__ uint32_t smem_u32(const void* p) {
    uint32_t a;
    asm("{ .reg .u64 t; cvta.to.shared.u64 t, %1; cvt.u32.u64 %0, t; }" : "=r"(a) : "l"(p));
    return a;
}
__device__ __forceinline__ void mma8(float* c, const uint32_t* a, const uint32_t* b) {
    asm volatile(
        "mma.sync.aligned.m16n8k8.row.col.f32.tf32.tf32.f32 "
        "{%0,%1,%2,%3}, {%4,%5,%6,%7}, {%8,%9}, {%0,%1,%2,%3};"
        : "+f"(c[0]), "+f"(c[1]), "+f"(c[2]), "+f"(c[3])
        : "r"(a[0]), "r"(a[1]), "r"(a[2]), "r"(a[3]), "r"(b[0]), "r"(b[1]));
}
__device__ __forceinline__ void mbar_init(uint32_t m, uint32_t cnt) {
    asm volatile("mbarrier.init.shared.b64 [%0], %1;" :: "r"(m), "r"(cnt) : "memory");
}
__device__ __forceinline__ void mbar_expect(uint32_t m, uint32_t bytes) {
    asm volatile("mbarrier.arrive.expect_tx.shared.b64 _, [%0], %1;"
                 :: "r"(m), "r"(bytes) : "memory");
}
__device__ __forceinline__ void mbar_wait(uint32_t m, uint32_t ph) {
    asm volatile(
        "{\n\t"
        ".reg .pred P1;\n\t"
        "LAB_%=:\n\t"
        "mbarrier.try_wait.parity.acquire.cta.shared::cta.b64 P1, [%0], %1, 0x989680;\n\t"
        "@P1 bra.uni DONE_%=;\n\t"
        "bra.uni LAB_%=;\n\t"
        "DONE_%=:\n\t"
        "}"
        :: "r"(m), "r"(ph) : "memory");
}
__device__ __forceinline__ void bulk_cp(uint32_t dst, const void* src,
                                        uint32_t bytes, uint32_t mbar) {
    asm volatile(
        "cp.async.bulk.shared::cluster.global.mbarrier::complete_tx::bytes "
        "[%0], [%1], %2, [%3];"
        :: "r"(dst), "l"(src), "r"(bytes), "r"(mbar) : "memory");
}

#define BB    8
#define CC    20
#define TT    15000
#define HW    625
#define CHS   872          // halo channel: 27 rows x 32 + 8 pad; halos stay zero

// interior pixel p -> halo layout offset
#define YXH(p) (((p) / 25) * 32 + ((p) % 25) + 33)

// memread MMA config: 288 blocks = one wave at 2 blocks/SM
#define NTS2  18
#define TSEG2 864          // 18*864 = 15552 >= 15000 (tail zero via guards)
#define TC2   32
#define QT2   2
#define QROWS 640

// scratch (device globals: allocation-free, zero-initialized at load;
// halo/pad regions are never written so they remain zero)
__device__ __align__(16) float g_y[BB * 40 * CHS];
__device__ __align__(16) float g_buf[2][2][BB * 256 * CHS];
__device__ __align__(16) float g_pa[BB * NTS2 * QROWS * 24];

// prepped weights, padded to smem-native stride 136: per chunk [72][136]
#define CHUNK_W 9792
#define ST_STRIDE 3858048     // 2*5*9792 + 6*2*32*9792
#define WPREP_TOTAL (2 * ST_STRIDE)
__device__ __align__(16) float g_wprep[WPREP_TOTAL];

// ---------------------------------------------------------------------------
// weight prep (transpose via smem) -> [kt 72][136] per chunk
// ---------------------------------------------------------------------------
__global__ void __launch_bounds__(256)
prep_weights2(const float* __restrict__ cls1_w,
              const float* __restrict__ clsk_w,
              const float* __restrict__ reg1_w,
              const float* __restrict__ regk_w) {
    __shared__ float smt[72 * 128];
    const int chunk = blockIdx.x;
    const int l = blockIdx.y;
    const int sb = blockIdx.z;
    const int s = sb >> 1, ocb = sb & 1;
    const int nch = (l == 0) ? 5 : 32;
    if (chunk >= nch) return;
    const int tid = threadIdx.x;

    const float* src;
    int srcK;
    if (l == 0) {
        src = s ? reg1_w : cls1_w; srcK = 360;
    } else {
        src = (s ? regk_w : clsk_w) + (size_t)(l - 1) * 256 * 2304; srcK = 2304;
    }

    {
        const int r = tid >> 1, part = tid & 1;
        const float4* srow = (const float4*)(src +
            (size_t)(ocb * 128 + r) * srcK + chunk * 72);
#pragma unroll
        for (int j4 = 0; j4 < 9; j4++) {
            float4 v = srow[part * 9 + j4];
            int j = (part * 9 + j4) * 4;
            smt[(j + 0) * 128 + r] = v.x;
            smt[(j + 1) * 128 + r] = v.y;
            smt[(j + 2) * 128 + r] = v.z;
            smt[(j + 3) * 128 + r] = v.w;
        }
    }
    __syncthreads();

    float* dst = g_wprep + (size_t)s * ST_STRIDE +
                 (l == 0 ? 0 : 97920 + (size_t)(l - 1) * 626688) +
                 (size_t)ocb * nch * CHUNK_W + (size_t)chunk * CHUNK_W;
#pragma unroll
    for (int it = 0; it < 36; it++) {
        int w_i = it * 256 + tid;
        int m = w_i & 127;
        int kt = w_i >> 7;              // tap*8 + k
        int tap = kt >> 3, k = kt & 7;
        dst[kt * 136 + m] = to_tf32(smt[(k * 9 + tap) * 128 + m]);
    }
}

// ---------------------------------------------------------------------------
// memory_read (pure tf32, log2-domain, dual-pipe exp); 2 blocks/SM, one wave.
// Staging: register-prefetch over THREE slots (768 = 3x256 < 3x320 entries;
// slot3 active for tid<128) — R16's bug was covering only 2 slots, leaving
// the ones/denominator channel uninitialized.
// ---------------------------------------------------------------------------
#define FMST 28
#define PST  36
#define MR_SMEM_FLOATS (TC2 * FMST + 10 * TC2 * PST)
#define MR_SMEM_BYTES (MR_SMEM_FLOATS * 4)

__global__ void __launch_bounds__(320, 2)
memread_mma(const float* __restrict__ fm, const float* __restrict__ fq) {
    extern __shared__ float ms[];
    float* fm_s = ms;
    const int tid = threadIdx.x;
    const int lane = tid & 31, w = tid >> 5;
    const int qt = blockIdx.x, ts = blockIdx.y, b = blockIdx.z;
    const int qbase = qt * 320 + w * 32;
    float* P = ms + TC2 * FMST + w * (TC2 * PST);

    const int mrow = lane >> 2;
    const int kcol = lane & 3;
    const float scale = 0.063758726f;          // log2(e)/sqrt(512)

    const ull C7 = pack2(1.5252734e-05f, 1.5252734e-05f);
    const ull C6 = pack2(1.5403530e-04f, 1.5403530e-04f);
    const ull C5 = pack2(1.3333558e-03f, 1.3333558e-03f);
    const ull C4 = pack2(9.6181291e-03f, 9.6181291e-03f);
    const ull C3 = pack2(5.5504109e-02f, 5.5504109e-02f);
    const ull C2 = pack2(2.4022651e-01f, 2.4022651e-01f);
    const ull C1 = pack2(6.9314718e-01f, 6.9314718e-01f);
    const ull ONE2 = pack2(1.0f, 1.0f);

    uint32_t a_f[2][3][4];
#pragma unroll
    for (int mf = 0; mf < 2; mf++)
#pragma unroll
        for (int kf = 0; kf < 3; kf++)
#pragma unroll
            for (int j = 0; j < 4; j++) {
                int q = qbase + 16 * mf + mrow + 8 * (j & 1);
                int c = kf * 8 + kcol + 4 * (j >> 1);
                float v = (q < HW && c < CC) ? fq[(b * CC + c) * HW + q] * scale : 0.f;
                a_f[mf][kf][j] = __float_as_uint(to_tf32(v));
            }

    float acc[2][3][4];
#pragma unroll
    for (int mf = 0; mf < 2; mf++)
#pragma unroll
        for (int nf = 0; nf < 3; nf++)
#pragma unroll
            for (int j = 0; j < 4; j++) acc[mf][nf][j] = 0.f;

    const int tseg0 = ts * TSEG2;
    const int NCH = TSEG2 / TC2;   // 27

    // per-thread staging slots: i = tid, tid+320, tid+640 (total 768 entries)
    const int i0 = tid, i1 = tid + 320, i2 = tid + 640;
    const int tl0 = i0 & 31, c0 = i0 >> 5;
    const int tl1 = i1 & 31, c1 = i1 >> 5;
    const int tl2 = i2 & 31, c2 = i2 >> 5;
    const bool v1 = (i1 < TC2 * 24);
    const bool v2 = (i2 < TC2 * 24);

    auto fetch = [&](int c, int tg) -> float {
        if (tg >= TT) return 0.f;
        if (c < CC) return fm[(size_t)(b * CC + c) * TT + tg];
        return (c == CC) ? 1.f : 0.f;
    };

    // prefetch chunk 0 into registers
    float pre0 = fetch(c0, tseg0 + tl0);
    float pre1 = v1 ? fetch(c1, tseg0 + tl1) : 0.f;
    float pre2 = v2 ? fetch(c2, tseg0 + tl2) : 0.f;

    for (int ch = 0; ch < NCH; ch++) {
        __syncthreads();                  // previous chunk's smem reads done
        fm_s[tl0 * FMST + c0] = pre0;
        if (v1) fm_s[tl1 * FMST + c1] = pre1;
        if (v2) fm_s[tl2 * FMST + c2] = pre2;
        __syncthreads();

        // issue next chunk's loads NOW; latency hides under the GEMMs below
        if (ch + 1 < NCH) {
            const int t0n = tseg0 + (ch + 1) * TC2;
            pre0 = fetch(c0, t0n + tl0);
            pre1 = v1 ? fetch(c1, t0n + tl1) : 0.f;
            pre2 = v2 ? fetch(c2, t0n + tl2) : 0.f;
        }

        // ---- GEMM1: z^T (32q x 32t)
        float s[2][4][4];
#pragma unroll
        for (int mf = 0; mf < 2; mf++)
#pragma unroll
            for (int nf = 0; nf < 4; nf++)
#pragma unroll
                for (int j = 0; j < 4; j++) s[mf][nf][j] = 0.f;

#pragma unroll
        for (int kf = 0; kf < 3; kf++) {
            uint32_t bh[4][2];
#pragma unroll
            for (int nf = 0; nf < 4; nf++) {
                int ta = (nf * 8 + mrow) * FMST + kf * 8 + kcol;
                bh[nf][0] = __float_as_uint(fm_s[ta]);
                bh[nf][1] = __float_as_uint(fm_s[ta + 4]);
            }
#pragma unroll
            for (int mf = 0; mf < 2; mf++)
#pragma unroll
                for (int nf = 0; nf < 4; nf++)
                    mma8(s[mf][nf], a_f[mf][kf], bh[nf]);
        }

        // ---- p = 2^z: dual-pipe exp
#pragma unroll
        for (int mf = 0; mf < 2; mf++) {
#pragma unroll
            for (int nf = 0; nf < 4; nf++) {
                float p0, p1, p2, p3;
                if (nf < 2) {
                    ull za = pack2(s[mf][nf][0], s[mf][nf][1]);
                    ull zb = pack2(s[mf][nf][2], s[mf][nf][3]);
                    ull ra = fma2(C7, za, C6);
                    ull rb = fma2(C7, zb, C6);
                    ra = fma2(ra, za, C5); rb = fma2(rb, zb, C5);
                    ra = fma2(ra, za, C4); rb = fma2(rb, zb, C4);
                    ra = fma2(ra, za, C3); rb = fma2(rb, zb, C3);
                    ra = fma2(ra, za, C2); rb = fma2(rb, zb, C2);
                    ra = fma2(ra, za, C1); rb = fma2(rb, zb, C1);
                    ra = fma2(ra, za, ONE2); rb = fma2(rb, zb, ONE2);
                    unpack2(ra, p0, p1);
                    unpack2(rb, p2, p3);
                } else {
                    p0 = ex2f(s[mf][nf][0]);
                    p1 = ex2f(s[mf][nf][1]);
                    p2 = ex2f(s[mf][nf][2]);
                    p3 = ex2f(s[mf][nf][3]);
                }
                int row = 16 * mf + mrow;
                int col = nf * 8 + 2 * kcol;
                P[row * PST + col] = p0;
                P[row * PST + col + 1] = p1;
                P[(row + 8) * PST + col] = p2;
                P[(row + 8) * PST + col + 1] = p3;
            }
        }
        __syncwarp();

        // ---- GEMM2: mem^T (32q x 24c2)
#pragma unroll
        for (int kf2 = 0; kf2 < 4; kf2++) {
            uint32_t ph[2][4];
#pragma unroll
            for (int mf = 0; mf < 2; mf++)
#pragma unroll
                for (int j = 0; j < 4; j++) {
                    int row = 16 * mf + mrow + 8 * (j & 1);
                    int col = kf2 * 8 + kcol + 4 * (j >> 1);
                    ph[mf][j] = __float_as_uint(P[row * PST + col]);
                }
            uint32_t bh2[3][2];
#pragma unroll
            for (int nf = 0; nf < 3; nf++) {
                int j0 = (kf2 * 8 + kcol) * FMST + nf * 8 + mrow;
                int j1 = (kf2 * 8 + kcol + 4) * FMST + nf * 8 + mrow;
                bh2[nf][0] = __float_as_uint(fm_s[j0]);
                bh2[nf][1] = __float_as_uint(fm_s[j1]);
            }
#pragma unroll
            for (int mf = 0; mf < 2; mf++)
#pragma unroll
                for (int nf = 0; nf < 3; nf++)
                    mma8(acc[mf][nf], ph[mf], bh2[nf]);
        }
    }

    const size_t base = (size_t)(b * NTS2 + ts) * QROWS;
#pragma unroll
    for (int mf = 0; mf < 2; mf++) {
        int row0 = qbase + 16 * mf + mrow;
#pragma unroll
        for (int nf = 0; nf < 3; nf++) {
            int col = nf * 8 + 2 * kcol;
            float2 v0 = make_float2(acc[mf][nf][0], acc[mf][nf][1]);
            float2 v1 = make_float2(acc[mf][nf][2], acc[mf][nf][3]);
            *(float2*)(g_pa + (base + row0) * 24 + col) = v0;
            *(float2*)(g_pa + (base + row0 + 8) * 24 + col) = v1;
        }
    }
}

// ---------------------------------------------------------------------------
// combine: writes interior of halo layout g_y
// ---------------------------------------------------------------------------
__global__ void memread_combine2(const float* __restrict__ fq) {
    const int b = blockIdx.y;
    if (threadIdx.x >= 125) return;
    const int q = blockIdx.x * 125 + threadIdx.x;
    const int yx = YXH(q);
    float num[20];
#pragma unroll
    for (int c = 0; c < CC; c++) num[c] = 0.f;
    float den = 0.f;
    for (int ts = 0; ts < NTS2; ts++) {
        const float4* p = (const float4*)(g_pa +
            ((size_t)(b * NTS2 + ts) * QROWS + q) * 24);
        float4 v0 = p[0], v1 = p[1], v2 = p[2], v3 = p[3], v4 = p[4], v5 = p[5];
        num[0] += v0.x; num[1] += v0.y; num[2] += v0.z; num[3] += v0.w;
        num[4] += v1.x; num[5] += v1.y; num[6] += v1.z; num[7] += v1.w;
        num[8] += v2.x; num[9] += v2.y; num[10] += v2.z; num[11] += v2.w;
        num[12] += v3.x; num[13] += v3.y; num[14] += v3.z; num[15] += v3.w;
        num[16] += v4.x; num[17] += v4.y; num[18] += v4.z; num[19] += v4.w;
        den += v5.x;
    }
    const float inv = 1.f / den;
#pragma unroll
    for (int c = 0; c < CC; c++)
        g_y[(b * 40 + c) * CHS + yx] = to_tf32(num[c] * inv);
#pragma unroll
    for (int c = 0; c < CC; c++)
        g_y[(b * 40 + 20 + c) * CHS + yx] = to_tf32(fq[(b * CC + c) * HW + q]);
}

// ---------------------------------------------------------------------------
// TF32 conv (R14 winner, unchanged): bulk staging + pipelined taps, 8 warps
// ---------------------------------------------------------------------------
#define TBF 6976           // B tile floats (8 * 872)
#define TAF 9792           // A tile floats (72 * 136)
#define OFF_B0 8
#define OFF_B1 (8 + TBF)
#define OFF_A0 (8 + 2 * TBF)
#define OFF_A1 (8 + 2 * TBF + TAF)
#define SMEM_FLOATS (8 + 2 * TBF + 2 * TAF)
#define SMEM_BYTES (SMEM_FLOATS * 4)
#define B_BYTES (TBF * 4)
#define A_BYTES (TAF * 4)

__device__ __forceinline__ void load_frags(
    const uint32_t* __restrict__ bAu32, const uint32_t* __restrict__ bBu32,
    int tap, int wm, int a_r, int a_c, const int* bslot, int kofs,
    uint32_t afr[4][4], uint32_t bfr[5][2]) {
    const int dy = tap / 3, dx = tap - 3 * (tap / 3);
    const int arow = (tap * 8 + a_c) * 136;
#pragma unroll
    for (int mf = 0; mf < 4; mf++) {
        int m0 = wm + mf * 16 + a_r;
        afr[mf][0] = bAu32[arow + m0];
        afr[mf][1] = bAu32[arow + m0 + 8];
        afr[mf][2] = bAu32[arow + 4 * 136 + m0];
        afr[mf][3] = bAu32[arow + 4 * 136 + m0 + 8];
    }
#pragma unroll
    for (int nf = 0; nf < 5; nf++) {
        int idx = kofs + bslot[nf] + dy * 32 + dx;
        bfr[nf][0] = bBu32[idx];
        bfr[nf][1] = bBu32[idx + 4 * 872];
    }
}

__global__ void __launch_bounds__(256, 1)
convgemm(const float* __restrict__ biasA, const float* __restrict__ biasB,
         int layer, int nch, int flags, int src, int dst) {
    extern __shared__ float sm[];
    const uint32_t sbase = smem_u32(sm);
    const uint32_t mbar0 = sbase;
    const uint32_t mbar1 = sbase + 8;

    const int tid = threadIdx.x;
    const int lane = tid & 31, wid = tid >> 5;    // 8 warps
    const int ocb = blockIdx.x & 1;
    const int px = blockIdx.x >> 1;               // 0..3
    const int b = blockIdx.y;
    const int st = blockIdx.z;

    const int wm = (wid & 1) * 64;                // 2 m-warps
    const int wn = (wid >> 1) * 40;               // 4 n-warps
    const int BN0 = px * 160;

    const float* in_ = (src < 0) ? (g_y + (size_t)b * 40 * CHS)
                                 : (&g_buf[st][src][(size_t)b * 256 * CHS]);
    float* out_ = &g_buf[st][dst][((size_t)b * 256 + ocb * 128) * CHS];
    const float* bias_ = (st ? biasB : biasA) + ocb * 128;
    const float* wl = g_wprep + (size_t)st * ST_STRIDE +
                      (layer == 0 ? 0 : 97920 + (size_t)(layer - 1) * 626688) +
                      (size_t)ocb * nch * CHUNK_W;

    if (tid == 0) {
        mbar_init(mbar0, 1);
        mbar_init(mbar1, 1);
        asm volatile("fence.proxy.async.shared::cta;" ::: "memory");
    }
    __syncthreads();

    const int a_r = lane >> 2;
    const int a_c = lane & 3;
    int bslot[5];
#pragma unroll
    for (int nf = 0; nf < 5; nf++) {
        int p = BN0 + wn + nf * 8 + a_r;
        int y = p / 25, x = p - 25 * y;
        bslot[nf] = y * 32 + x;
    }
    const int kofs = a_c * 872;

    float cr[4][5][4];
#pragma unroll
    for (int mf = 0; mf < 4; mf++)
#pragma unroll
        for (int nf = 0; nf < 5; nf++)
#pragma unroll
            for (int j = 0; j < 4; j++) cr[mf][nf][j] = 0.f;

    if (tid == 0) {
        mbar_expect(mbar0, B_BYTES + A_BYTES);
        bulk_cp(sbase + OFF_B0 * 4, in_, B_BYTES, mbar0);
        bulk_cp(sbase + OFF_A0 * 4, wl, A_BYTES, mbar0);
    }

    for (int c = 0; c < nch; c++) {
        const int p = c & 1;
        if (c + 1 < nch) {
            if (tid == 0) {
                uint32_t mb = p ? mbar0 : mbar1;
                mbar_expect(mb, B_BYTES + A_BYTES);
                bulk_cp(sbase + (p ? OFF_B0 : OFF_B1) * 4,
                        in_ + (size_t)(c + 1) * 8 * CHS, B_BYTES, mb);
                bulk_cp(sbase + (p ? OFF_A0 : OFF_A1) * 4,
                        wl + (size_t)(c + 1) * CHUNK_W, A_BYTES, mb);
            }
        }
        mbar_wait(p ? mbar1 : mbar0, (c >> 1) & 1);

        const uint32_t* bBu32 = (const uint32_t*)(sm + (p ? OFF_B1 : OFF_B0));
        const uint32_t* bAu32 = (const uint32_t*)(sm + (p ? OFF_A1 : OFF_A0));

        uint32_t afr[2][4][4], bfr[2][5][2];
        load_frags(bAu32, bBu32, 0, wm, a_r, a_c, bslot, kofs, afr[0], bfr[0]);
#pragma unroll
        for (int tap = 0; tap < 9; tap++) {
            const int cur = tap & 1;
            if (tap < 8)
                load_frags(bAu32, bBu32, tap + 1, wm, a_r, a_c, bslot, kofs,
                           afr[cur ^ 1], bfr[cur ^ 1]);
#pragma unroll
            for (int mf = 0; mf < 4; mf++)
#pragma unroll
                for (int nf = 0; nf < 5; nf++)
                    mma8(cr[mf][nf], afr[cur][mf], bfr[cur][nf]);
        }
        __syncthreads();
    }

    const int ccol = (lane & 3) * 2;
    const bool relu = flags & 1, rnd = flags & 2;
#pragma unroll
    for (int mf = 0; mf < 4; mf++) {
        int r0 = wm + mf * 16 + a_r;
        float bv0 = bias_[r0], bv1 = bias_[r0 + 8];
        float* o0 = out_ + (size_t)r0 * CHS;
        float* o1 = o0 + (size_t)8 * CHS;
#pragma unroll
        for (int nf = 0; nf < 5; nf++) {
            int p = BN0 + wn + nf * 8 + ccol;
            float v0 = cr[mf][nf][0] + bv0;
            float v1 = cr[mf][nf][1] + bv0;
            float v2 = cr[mf][nf][2] + bv1;
            float v3 = cr[mf][nf][3] + bv1;
            if (relu) {
                v0 = fmaxf(v0, 0.f); v1 = fmaxf(v1, 0.f);
                v2 = fmaxf(v2, 0.f); v3 = fmaxf(v3, 0.f);
            }
            if (rnd) {
                v0 = to_tf32(v0); v1 = to_tf32(v1);
                v2 = to_tf32(v2); v3 = to_tf32(v3);
            }
            if (p < HW) {
                int yx = YXH(p);
                o0[yx] = v0; o1[yx] = v2;
            }
            if (p + 1 < HW) {
                int yx1 = YXH(p + 1);
                o0[yx1] = v1; o1[yx1] = v3;
            }
        }
    }
}

// ---------------------------------------------------------------------------
// heads (halo-layout reads)
// ---------------------------------------------------------------------------
__global__ void head_kernel(
    const float* __restrict__ w_cls, const float* __restrict__ b_cls,
    const float* __restrict__ g_cls, const float* __restrict__ be_cls,
    const float* __restrict__ w_ctr, const float* __restrict__ b_ctr,
    const float* __restrict__ g_ctr, const float* __restrict__ be_ctr,
    const float* __restrict__ w_off, const float* __restrict__ b_off,
    const float* __restrict__ g_off, const float* __restrict__ be_off,
    const float* __restrict__ si, const float* __restrict__ bi,
    float* __restrict__ out) {
    const int b = blockIdx.y;
    const int tid = threadIdx.x;
    __shared__ float sw[6 * 256];
    for (int i = tid; i < 256; i += 128) {
        sw[i] = w_cls[i];
        sw[256 + i] = w_ctr[i];
#pragma unroll
        for (int j = 0; j < 4; j++) sw[(2 + j) * 256 + i] = w_off[j * 256 + i];
    }
    __syncthreads();
    if (tid >= 125) return;

    const int p = blockIdx.x * 125 + tid;
    const int yx = YXH(p);
    const float rsq = rsqrtf(1.f + 1e-5f);
    const float scls = g_cls[0] * rsq, sctr = g_ctr[0] * rsq;
    const float sV = si[0], bV = bi[0];

    float d0 = 0, d1 = 0, d2 = 0, d3 = 0, d4 = 0, d5 = 0;
    const float* fc = g_buf[0][0] + (size_t)(b * 256) * CHS + yx;
    const float* fr = g_buf[1][0] + (size_t)(b * 256) * CHS + yx;
#pragma unroll 4
    for (int c = 0; c < 256; c++) {
        float vc = fc[(size_t)c * CHS];
        float vr = fr[(size_t)c * CHS];
        d0 += vc * sw[c];
        d1 += vc * sw[256 + c];
        d2 += vr * sw[512 + c];
        d3 += vr * sw[768 + c];
        d4 += vr * sw[1024 + c];
        d5 += vr * sw[1280 + c];
    }
    float cls = (d0 + b_cls[0]) * scls + be_cls[0];
    float ctr = (d1 + b_ctr[0]) * sctr + be_ctr[0];
    float dd[4] = {d2, d3, d4, d5};
    float off[4];
#pragma unroll
    for (int j = 0; j < 4; j++) {
        float bn = (dd[j] + b_off[j]) * (g_off[j] * rsq) + be_off[j];
        off[j] = expf(sV * bn + bV) * 8.f;
    }
    float gx = 3.f + 8.f * (float)(p % 25);
    float gy = 3.f + 8.f * (float)(p / 25);
    int qi = b * HW + p;
    out[qi] = cls;
    out[5000 + qi] = ctr;
    float* bb = out + 10000 + (size_t)qi * 4;
    bb[0] = gx - off[0];
    bb[1] = gy - off[1];
    bb[2] = gx + off[2];
    bb[3] = gy + off[3];
}

// ---------------------------------------------------------------------------
extern "C" void kernel_launch(void* const* d_in, const int* in_sizes, int n_in,
                              void* d_out, int out_size) {
    const float* fm     = (const float*)d_in[0];
    const float* fq     = (const float*)d_in[1];
    const float* cls1_w = (const float*)d_in[2];
    const float* cls1_b = (const float*)d_in[3];
    const float* clsk_w = (const float*)d_in[4];
    const float* clsk_b = (const float*)d_in[5];
    const float* reg1_w = (const float*)d_in[6];
    const float* reg1_b = (const float*)d_in[7];
    const float* regk_w = (const float*)d_in[8];
    const float* regk_b = (const float*)d_in[9];
    const float* w_cls  = (const float*)d_in[10];
    const float* b_cls  = (const float*)d_in[11];
    const float* g_cls  = (const float*)d_in[12];
    const float* be_cls = (const float*)d_in[13];
    const float* w_ctr  = (const float*)d_in[14];
    const float* b_ctr  = (const float*)d_in[15];
    const float* g_ctr  = (const float*)d_in[16];
    const float* be_ctr = (const float*)d_in[17];
    const float* w_off  = (const float*)d_in[18];
    const float* b_off  = (const float*)d_in[19];
    const float* g_off  = (const float*)d_in[20];
    const float* be_off = (const float*)d_in[21];
    const float* si     = (const float*)d_in[22];
    const float* bi     = (const float*)d_in[23];
    float* out = (float*)d_out;

    cudaFuncSetAttribute(convgemm, cudaFuncAttributeMaxDynamicSharedMemorySize,
                         SMEM_BYTES);
    cudaFuncSetAttribute(memread_mma, cudaFuncAttributeMaxDynamicSharedMemorySize,
                         MR_SMEM_BYTES);

    // launch order: prep(1) memread(2) combine(3) conv1(4 = ncu capture slot)
    prep_weights2<<<dim3(32, 7, 4), 256>>>(cls1_w, clsk_w, reg1_w, regk_w);

    memread_mma<<<dim3(QT2, NTS2, BB), 320, MR_SMEM_BYTES>>>(fm, fq);
    memread_combine2<<<dim3(5, BB), 128>>>(fq);

    // conv1: Cin=40 (5 chunks), output relu+round, g_y -> buf 0
    convgemm<<<dim3(8, BB, 2), 256, SMEM_BYTES>>>(cls1_b, reg1_b, 0, 5, 3, -1, 0);

    // 6 x conv 256->256, ping-pong; final layer raw
    for (int i = 0; i < 6; i++) {
        convgemm<<<dim3(8, BB, 2), 256, SMEM_BYTES>>>(
            clsk_b + i * 256, regk_b + i * 256,
            i + 1, 32, (i < 5) ? 3 : 0, i % 2, (i + 1) % 2);
    }

    head_kernel<<<dim3(5, BB), 128>>>(w_cls, b_cls, g_cls, be_cls,
                                      w_ctr, b_ctr, g_ctr, be_ctr,
                                      w_off, b_off, g_off, be_off,
                                      si, bi, out);
}